// round 6
// baseline (speedup 1.0000x reference)
#include <cuda_runtime.h>
#include <cuda_bf16.h>
#include <math.h>

typedef unsigned long long ull;

// Problem constants
#define BB 1
#define CC 32
#define HH 128
#define WW 160
#define DD 48
#define HW (HH*WW)          // 20480

// Padded per-(dz,dy) partial volumes U: (9, D+2, H+2, W) — no w halo (dx folded)
#define PD (DD+2)           // 50
#define PH (HH+2)           // 130
#define ROWS   160
#define SLICE  (PH*ROWS)    // 20800
#define CSTS   (PD*SLICE)   // 1,040,000 per volume

// Device globals zero-initialized at module load; halo cells of g_S are never
// written, so SAME-padding zeros in d/h are free and persistent.
__device__ float g_rot[2][9];
__device__ float g_trans[2][3];
__device__ float g_featT[3][HW*CC];          // (view, y, x, c) channel-last
__device__ float g_S[9u*CSTS];               // 9 padded partial volumes ~37MB
__device__ float g_cost[DD*HW];              // ~3.9 MB

#define FFMA2(d, a, b, c) \
    asm("fma.rn.f32x2 %0, %1, %2, %3;" : "=l"(d) : "l"(a), "l"(b), "l"(c))
#define PACK2(out, lo, hi) \
    asm("mov.b64 %0, {%1, %2};" : "=l"(out) : "f"(lo), "f"(hi))
#define UNPACK2(lo, hi, in) \
    asm("mov.b64 {%0, %1}, %2;" : "=f"(lo), "=f"(hi) : "l"(in))

// Dynamic smem layout (bytes):
//  Region A (union, temporally disjoint):
//    Phase A/B: s_wgt float4[2rows][2views][160] @0      (10240)
//               s_adr int4  [2][2][160]          @10240  (10240)
//    Phase D:   s_e0 float[2][9][162]            @0      (11664)
//               s_e2 float[2][9][162]            @11664  (11664)
//  s_var float[2][160][36]  @23328  (46080)   (w*144B -> 16B aligned)
//  s_pwt ull[27*16]         @69408  (3456)
#define OFF_WGT 0
#define OFF_ADR 10240
#define OFF_E0  0
#define OFF_E2  11664
#define OFF_VAR 23328
#define OFF_PWT 69408
#define SMEM_BYTES 72864

// ---------------------------------------------------------------------------
// Stage 0: proj_v @ inv(proj_ref) -> rot(3x3), trans(3) for views 1,2
// ---------------------------------------------------------------------------
__global__ void prep_kernel(const float* __restrict__ proj)
{
    if (threadIdx.x != 0 || blockIdx.x != 0) return;
    float A0[9], b0[3];
    for (int r = 0; r < 3; ++r) {
        for (int c = 0; c < 3; ++c) A0[r*3+c] = proj[r*4+c];
        b0[r] = proj[r*4+3];
    }
    float inv[9];
    inv[0] =  A0[4]*A0[8] - A0[5]*A0[7];
    inv[1] = -(A0[1]*A0[8] - A0[2]*A0[7]);
    inv[2] =  A0[1]*A0[5] - A0[2]*A0[4];
    inv[3] = -(A0[3]*A0[8] - A0[5]*A0[6]);
    inv[4] =  A0[0]*A0[8] - A0[2]*A0[6];
    inv[5] = -(A0[0]*A0[5] - A0[2]*A0[3]);
    inv[6] =  A0[3]*A0[7] - A0[4]*A0[6];
    inv[7] = -(A0[0]*A0[7] - A0[1]*A0[6]);
    inv[8] =  A0[0]*A0[4] - A0[1]*A0[3];
    float det = A0[0]*inv[0] + A0[1]*inv[3] + A0[2]*inv[6];
    float idet = 1.0f / det;
    for (int i = 0; i < 9; ++i) inv[i] *= idet;

    for (int v = 1; v < 3; ++v) {
        const float* P = proj + v*16;
        float Av[9], bv[3];
        for (int r = 0; r < 3; ++r) {
            for (int c = 0; c < 3; ++c) Av[r*3+c] = P[r*4+c];
            bv[r] = P[r*4+3];
        }
        float rot[9];
        for (int r = 0; r < 3; ++r)
            for (int c = 0; c < 3; ++c)
                rot[r*3+c] = Av[r*3+0]*inv[0*3+c] + Av[r*3+1]*inv[1*3+c] + Av[r*3+2]*inv[2*3+c];
        for (int r = 0; r < 3; ++r)
            g_trans[v-1][r] = bv[r] - (rot[r*3+0]*b0[0] + rot[r*3+1]*b0[1] + rot[r*3+2]*b0[2]);
        for (int i = 0; i < 9; ++i) g_rot[v-1][i] = rot[i];
    }
}

// ---------------------------------------------------------------------------
// Stage 1: tiled transpose (C,H,W) -> (H,W,C) for all 3 views.
// ---------------------------------------------------------------------------
__global__ void transpose_kernel(const float* __restrict__ f0,
                                 const float* __restrict__ f1,
                                 const float* __restrict__ f2)
{
    __shared__ float t[32][33];
    int v  = blockIdx.y;
    int p0 = blockIdx.x * 32;
    int tx = threadIdx.x, ty = threadIdx.y;
    const float* src = (v == 0) ? f0 : (v == 1) ? f1 : f2;

#pragma unroll
    for (int j = ty; j < 32; j += 8)
        t[j][tx] = src[j*HW + p0 + tx];
    __syncthreads();
#pragma unroll
    for (int j = ty; j < 32; j += 8)
        g_featT[v][(p0 + j)*CC + tx] = t[tx][j];
}

// ---------------------------------------------------------------------------
// Stage 2: warp + variance + fused channel GEMM + dx-fold, DUAL depth rows.
// Block per (h, d-pair), 256 threads, ~71KB smem -> 2 blocks/SM.
//  A: bilinear weights + addresses for 2 rows x 2 views x 160 w.
//  B: half-warp = voxel, lane = channel pair: LDG.64 corner gathers; ref
//     features loaded once, reused for both depth rows.
//  D: thread = w: weights loaded ONCE per k and applied to BOTH rows
//     (weight LDS halved); dx-folded into 9 U values per row via smem edges.
// ---------------------------------------------------------------------------
__global__ void __launch_bounds__(256, 2)
warp_var_kernel(const float* __restrict__ depth_values,
                const float* __restrict__ w_reg)
{
    extern __shared__ char smraw[];
    float4* s_wgt = (float4*)(smraw + OFF_WGT);   // [(r*2+v)*160 + w]
    int4*   s_adr = (int4*)  (smraw + OFF_ADR);
    float*  s_var = (float*) (smraw + OFF_VAR);   // r*5760 + w*36 + c
    ull*    s_pwt = (ull*)   (smraw + OFF_PWT);   // k*16 + c2
    float*  s_e0  = (float*) (smraw + OFF_E0);    // (r*9+k9)*162 + idx
    float*  s_e2  = (float*) (smraw + OFF_E2);

    int h  = blockIdx.x;
    int d0 = blockIdx.y * 2;
    int tid = threadIdx.x;

    // ---- Phase A: projection coords for 2 rows x 2 views x 160 w ----
    for (int t = tid; t < 640; t += 256) {
        int r   = t / 320;
        int rem = t - r*320;
        int v   = rem / 160;
        int w   = rem - v*160;
        float depth = __ldg(depth_values + d0 + r);
        float fx = (float)w, fy = (float)h;

        float px = (g_rot[v][0]*fx + g_rot[v][1]*fy + g_rot[v][2]) * depth + g_trans[v][0];
        float py = (g_rot[v][3]*fx + g_rot[v][4]*fy + g_rot[v][5]) * depth + g_trans[v][1];
        float pz = (g_rot[v][6]*fx + g_rot[v][7]*fy + g_rot[v][8]) * depth + g_trans[v][2];
        float gx = px / pz;
        float gy = py / pz;

        float x0f = floorf(gx), y0f = floorf(gy);
        float wx = gx - x0f, wy = gy - y0f;
        float x1f = x0f + 1.0f, y1f = y0f + 1.0f;

        float vx0 = (x0f >= 0.0f && x0f <= (float)(WW-1)) ? 1.0f : 0.0f;
        float vx1 = (x1f >= 0.0f && x1f <= (float)(WW-1)) ? 1.0f : 0.0f;
        float vy0 = (y0f >= 0.0f && y0f <= (float)(HH-1)) ? 1.0f : 0.0f;
        float vy1 = (y1f >= 0.0f && y1f <= (float)(HH-1)) ? 1.0f : 0.0f;

        float w00 = (1.0f-wx)*(1.0f-wy) * (vx0*vy0);
        float w10 = wx*(1.0f-wy)        * (vx1*vy0);
        float w01 = (1.0f-wx)*wy        * (vx0*vy1);
        float w11 = wx*wy               * (vx1*vy1);

        int x0 = (int)fminf(fmaxf(x0f, 0.0f), (float)(WW-1));
        int x1 = (int)fminf(fmaxf(x1f, 0.0f), (float)(WW-1));
        int y0 = (int)fminf(fmaxf(y0f, 0.0f), (float)(HH-1));
        int y1 = (int)fminf(fmaxf(y1f, 0.0f), (float)(HH-1));

        int si = (r*2 + v)*160 + w;
        s_wgt[si] = make_float4(w00, w10, w01, w11);
        s_adr[si] = make_int4((y0*WW + x0)*16, (y0*WW + x1)*16,
                              (y1*WW + x0)*16, (y1*WW + x1)*16);
    }

    // Packed weights: s_pwt[k*16+c2] = (wt[2c2][k], wt[2c2+1][k])
    for (int i = tid; i < 27*16; i += 256) {
        int k  = i >> 4;
        int c2 = i & 15;
        float lo = __ldg(w_reg + (2*c2    )*27 + k);
        float hi = __ldg(w_reg + (2*c2 + 1)*27 + k);
        ull p; PACK2(p, lo, hi);
        s_pwt[i] = p;
    }
    __syncthreads();

    // ---- Phase B: paired-voxel float2 gathers + variance, both rows ----
    {
        int lane = tid & 31;
        int warp = tid >> 5;
        int half = lane >> 4;          // which voxel of the pair
        int c2   = lane & 15;          // channel pair index

        const float2* F0 = (const float2*)g_featT[0];
        const float2* F1 = (const float2*)g_featT[1];
        const float2* F2 = (const float2*)g_featT[2];

        // ref features: d-independent, load once for both rows
        float2 refs[10];
#pragma unroll
        for (int i = 0; i < 10; ++i) {
            int w = warp*20 + 2*i + half;
            refs[i] = __ldg(F0 + (h*WW + w)*16 + c2);
        }

#pragma unroll
        for (int r = 0; r < 2; ++r) {
            const float4* wgt = s_wgt + (r*2)*160;
            const int4*   adr = s_adr + (r*2)*160;
            float* vr = s_var + r*5760;
#pragma unroll 5
            for (int i = 0; i < 10; ++i) {
                int w = warp*20 + 2*i + half;

                float2 ref = refs[i];
                float sx = ref.x, sy = ref.y;
                float qx = ref.x*ref.x, qy = ref.y*ref.y;

                {
                    float4 wt = wgt[w];
                    int4   ad = adr[w];
                    float2 a = __ldg(F1 + ad.x + c2);
                    float2 b = __ldg(F1 + ad.y + c2);
                    float2 c = __ldg(F1 + ad.z + c2);
                    float2 e = __ldg(F1 + ad.w + c2);
                    float fxv = wt.x*a.x + wt.y*b.x + wt.z*c.x + wt.w*e.x;
                    float fyv = wt.x*a.y + wt.y*b.y + wt.z*c.y + wt.w*e.y;
                    sx += fxv; qx += fxv*fxv;
                    sy += fyv; qy += fyv*fyv;
                }
                {
                    float4 wt = wgt[160 + w];
                    int4   ad = adr[160 + w];
                    float2 a = __ldg(F2 + ad.x + c2);
                    float2 b = __ldg(F2 + ad.y + c2);
                    float2 c = __ldg(F2 + ad.z + c2);
                    float2 e = __ldg(F2 + ad.w + c2);
                    float fxv = wt.x*a.x + wt.y*b.x + wt.z*c.x + wt.w*e.x;
                    float fyv = wt.x*a.y + wt.y*b.y + wt.z*c.y + wt.w*e.y;
                    sx += fxv; qx += fxv*fxv;
                    sy += fyv; qy += fyv*fyv;
                }

                const float inv3 = (1.0f/3.0f);
                float mx = sx * inv3, my = sy * inv3;
                float2 var = make_float2(qx*inv3 - mx*mx, qy*inv3 - my*my);
                *(float2*)(vr + w*36 + 2*c2) = var;
            }
        }
    }
    __syncthreads();   // after this, s_wgt/s_adr are dead -> region becomes edges

    // zero fold-edge boundary cells (2 rows x 9 x 2 edges)
    if (tid < 36) {
        int r  = tid / 18;
        int q  = tid - r*18;
        int a  = q / 9;
        int k9 = q - a*9;
        if (a) s_e2[(r*9 + k9)*162 + 160] = 0.0f;
        else   s_e0[(r*9 + k9)*162 + 0]   = 0.0f;
    }

    // ---- Phase D: dual-row channel GEMM (weights loaded once per k) ----
    float S1a[9], S1b[9];
    if (tid < WW) {
        int w = tid;
        ull va[16], vb[16];
        const ulonglong2* qa = (const ulonglong2*)(s_var + w*36);
        const ulonglong2* qb = (const ulonglong2*)(s_var + 5760 + w*36);
#pragma unroll
        for (int j = 0; j < 8; ++j) {
            ulonglong2 pa = qa[j], pb = qb[j];
            va[2*j] = pa.x; va[2*j+1] = pa.y;
            vb[2*j] = pb.x; vb[2*j+1] = pb.y;
        }

#pragma unroll
        for (int k = 0; k < 27; ++k) {
            const ulonglong2* pw = (const ulonglong2*)(s_pwt + k*16);
            ull aA = 0ull, aB = 0ull, bA = 0ull, bB = 0ull;
#pragma unroll
            for (int c2 = 0; c2 < 8; ++c2) {
                ulonglong2 wp = pw[c2];
                FFMA2(aA, va[2*c2],   wp.x, aA);
                FFMA2(aB, va[2*c2+1], wp.y, aB);
                FFMA2(bA, vb[2*c2],   wp.x, bA);
                FFMA2(bB, vb[2*c2+1], wp.y, bB);
            }
            float x0, x1, y0, y1;
            UNPACK2(x0, x1, aA); UNPACK2(y0, y1, aB);
            float Sa = (x0 + x1) + (y0 + y1);
            UNPACK2(x0, x1, bA); UNPACK2(y0, y1, bB);
            float Sb = (x0 + x1) + (y0 + y1);

            int k9 = k / 3, dx = k - k9*3;
            if (dx == 0) {
                s_e0[(0*9 + k9)*162 + w + 1] = Sa;
                s_e0[(1*9 + k9)*162 + w + 1] = Sb;
            } else if (dx == 1) {
                S1a[k9] = Sa; S1b[k9] = Sb;
            } else {
                s_e2[(0*9 + k9)*162 + w] = Sa;
                s_e2[(1*9 + k9)*162 + w] = Sb;
            }
        }
    }
    __syncthreads();

    if (tid < WW) {
        int w = tid;
        size_t base = (size_t)(d0 + 1)*SLICE + (h + 1)*ROWS + w;
#pragma unroll
        for (int k9 = 0; k9 < 9; ++k9) {
            float Ua = s_e0[(0*9 + k9)*162 + w] + S1a[k9] + s_e2[(0*9 + k9)*162 + w + 1];
            float Ub = s_e0[(1*9 + k9)*162 + w] + S1b[k9] + s_e2[(1*9 + k9)*162 + w + 1];
            g_S[(size_t)k9*CSTS + base]         = Ua;
            g_S[(size_t)k9*CSTS + base + SLICE] = Ub;
        }
    }
}

// ---------------------------------------------------------------------------
// Stage 3: 9-tap shifted-sum of partial volumes -> cost, float4-vectorized.
// cost(d,h,w) = sum_{dz,dy} U_{dz,dy}(padded d+dz, h+dy, w)
// ---------------------------------------------------------------------------
__global__ void __launch_bounds__(256)
sum_kernel()
{
    int idx = blockIdx.x * 256 + threadIdx.x;      // DD*HH*WW/4 = 245760
    int w4 = idx % 40;
    int t  = idx / 40;
    int h  = t % HH;
    int d  = t / HH;

    const float* base = g_S + (size_t)d*SLICE + h*ROWS + w4*4;
    float ax = 0.0f, ay = 0.0f, az = 0.0f, aw = 0.0f;
#pragma unroll
    for (int k9 = 0; k9 < 9; ++k9) {
        int dz = k9 / 3, dy = k9 - dz*3;
        float4 v = *(const float4*)(base + (size_t)k9*CSTS + dz*SLICE + dy*ROWS);
        ax += v.x; ay += v.y; az += v.z; aw += v.w;
    }
    *(float4*)(g_cost + d*HW + h*WW + w4*4) = make_float4(ax, ay, az, aw);
}

// ---------------------------------------------------------------------------
// Stage 4: softmax over D, expected depth + max-prob confidence.
// b_reg shifts all logits equally -> cancels in softmax -> ignored.
// ---------------------------------------------------------------------------
__global__ void __launch_bounds__(128)
depth_kernel(const float* __restrict__ depth_values, float* __restrict__ out)
{
    int pix = blockIdx.x * 128 + threadIdx.x;
    if (pix >= HW) return;

    float cv[DD];
    float m = -1e30f;
#pragma unroll
    for (int d = 0; d < DD; ++d) {
        cv[d] = g_cost[d*HW + pix];
        m = fmaxf(m, cv[d]);
    }
    float sum = 0.0f, dep = 0.0f, best = 0.0f;
#pragma unroll
    for (int d = 0; d < DD; ++d) {
        float e = expf(cv[d] - m);
        sum += e;
        dep += e * __ldg(depth_values + d);
        best = fmaxf(best, e);
    }
    float isum = 1.0f / sum;
    out[pix]      = dep * isum;
    out[HW + pix] = best * isum;
}

// ---------------------------------------------------------------------------
extern "C" void kernel_launch(void* const* d_in, const int* in_sizes, int n_in,
                              void* d_out, int out_size)
{
    const float* feat0 = (const float*)d_in[0];
    const float* feat1 = (const float*)d_in[1];
    const float* feat2 = (const float*)d_in[2];
    const float* proj  = (const float*)d_in[3];
    const float* dvals = (const float*)d_in[4];
    const float* wreg  = (const float*)d_in[5];
    float* out = (float*)d_out;

    cudaFuncSetAttribute(warp_var_kernel,
                         cudaFuncAttributeMaxDynamicSharedMemorySize, SMEM_BYTES);

    prep_kernel<<<1, 1>>>(proj);
    transpose_kernel<<<dim3(HW/32, 3), dim3(32, 8)>>>(feat0, feat1, feat2);
    warp_var_kernel<<<dim3(HH, DD/2), 256, SMEM_BYTES>>>(dvals, wreg);
    sum_kernel<<<(DD*HH*WW/4 + 255)/256, 256>>>();
    depth_kernel<<<(HW + 127)/128, 128>>>(dvals, out);
}

// round 7
// speedup vs baseline: 1.0060x; 1.0060x over previous
#include <cuda_runtime.h>
#include <cuda_bf16.h>
#include <math.h>

typedef unsigned long long ull;

// Problem constants
#define BB 1
#define CC 32
#define HH 128
#define WW 160
#define DD 48
#define HW (HH*WW)          // 20480

// Padded per-(dz,dy) partial volumes U: (9, D+2, H+2, W) — no w halo (dx folded)
#define PD (DD+2)           // 50
#define PH (HH+2)           // 130
#define ROWS   160
#define SLICE  (PH*ROWS)    // 20800
#define CSTS   (PD*SLICE)   // 1,040,000 per volume

// Device globals zero-initialized at module load; halo cells of g_S are never
// written, so SAME-padding zeros in d/h are free and persistent.
__device__ float g_rot[2][9];
__device__ float g_trans[2][3];
__device__ float g_featT[3][HW*CC];          // (view, y, x, c) channel-last
__device__ float g_S[9u*CSTS];               // 9 padded partial volumes ~37MB
__device__ float g_cost[DD*HW];              // ~3.9 MB

#define FFMA2(d, a, b, c) \
    asm("fma.rn.f32x2 %0, %1, %2, %3;" : "=l"(d) : "l"(a), "l"(b), "l"(c))
#define PACK2(out, lo, hi) \
    asm("mov.b64 %0, {%1, %2};" : "=l"(out) : "f"(lo), "f"(hi))
#define UNPACK2(lo, hi, in) \
    asm("mov.b64 {%0, %1}, %2;" : "=f"(lo), "=f"(hi) : "l"(in))

// Dynamic smem layout (bytes):
//  Region A (union, temporally disjoint):
//    Phase A/B: s_wgt float4[2rows][2views][160] @0      (10240)
//               s_adr int4  [2][2][160]          @10240  (10240)
//    Phase D:   s_e0 float[2][9][162]            @0      (11664)
//               s_e2 float[2][9][162]            @11664  (11664)
//  s_var float[2][160][36]  @23328  (46080)   (w*144B -> 16B aligned)
//  s_pwt ull[27*16]         @69408  (3456)
#define OFF_WGT 0
#define OFF_ADR 10240
#define OFF_E0  0
#define OFF_E2  11664
#define OFF_VAR 23328
#define OFF_PWT 69408
#define SMEM_BYTES 72864

// ---------------------------------------------------------------------------
// Stage 0: proj_v @ inv(proj_ref) -> rot(3x3), trans(3) for views 1,2
// ---------------------------------------------------------------------------
__global__ void prep_kernel(const float* __restrict__ proj)
{
    if (threadIdx.x != 0 || blockIdx.x != 0) return;
    float A0[9], b0[3];
    for (int r = 0; r < 3; ++r) {
        for (int c = 0; c < 3; ++c) A0[r*3+c] = proj[r*4+c];
        b0[r] = proj[r*4+3];
    }
    float inv[9];
    inv[0] =  A0[4]*A0[8] - A0[5]*A0[7];
    inv[1] = -(A0[1]*A0[8] - A0[2]*A0[7]);
    inv[2] =  A0[1]*A0[5] - A0[2]*A0[4];
    inv[3] = -(A0[3]*A0[8] - A0[5]*A0[6]);
    inv[4] =  A0[0]*A0[8] - A0[2]*A0[6];
    inv[5] = -(A0[0]*A0[5] - A0[2]*A0[3]);
    inv[6] =  A0[3]*A0[7] - A0[4]*A0[6];
    inv[7] = -(A0[0]*A0[7] - A0[1]*A0[6]);
    inv[8] =  A0[0]*A0[4] - A0[1]*A0[3];
    float det = A0[0]*inv[0] + A0[1]*inv[3] + A0[2]*inv[6];
    float idet = 1.0f / det;
    for (int i = 0; i < 9; ++i) inv[i] *= idet;

    for (int v = 1; v < 3; ++v) {
        const float* P = proj + v*16;
        float Av[9], bv[3];
        for (int r = 0; r < 3; ++r) {
            for (int c = 0; c < 3; ++c) Av[r*3+c] = P[r*4+c];
            bv[r] = P[r*4+3];
        }
        float rot[9];
        for (int r = 0; r < 3; ++r)
            for (int c = 0; c < 3; ++c)
                rot[r*3+c] = Av[r*3+0]*inv[0*3+c] + Av[r*3+1]*inv[1*3+c] + Av[r*3+2]*inv[2*3+c];
        for (int r = 0; r < 3; ++r)
            g_trans[v-1][r] = bv[r] - (rot[r*3+0]*b0[0] + rot[r*3+1]*b0[1] + rot[r*3+2]*b0[2]);
        for (int i = 0; i < 9; ++i) g_rot[v-1][i] = rot[i];
    }
}

// ---------------------------------------------------------------------------
// Stage 1: tiled transpose (C,H,W) -> (H,W,C) for all 3 views.
// ---------------------------------------------------------------------------
__global__ void transpose_kernel(const float* __restrict__ f0,
                                 const float* __restrict__ f1,
                                 const float* __restrict__ f2)
{
    __shared__ float t[32][33];
    int v  = blockIdx.y;
    int p0 = blockIdx.x * 32;
    int tx = threadIdx.x, ty = threadIdx.y;
    const float* src = (v == 0) ? f0 : (v == 1) ? f1 : f2;

#pragma unroll
    for (int j = ty; j < 32; j += 8)
        t[j][tx] = src[j*HW + p0 + tx];
    __syncthreads();
#pragma unroll
    for (int j = ty; j < 32; j += 8)
        g_featT[v][(p0 + j)*CC + tx] = t[tx][j];
}

// ---------------------------------------------------------------------------
// Stage 2: warp + variance + fused channel GEMM + dx-fold, DUAL depth rows.
// Block per (h, d-pair), 256 threads, ~71KB smem -> 2 blocks/SM.
//  A: bilinear weights + addresses for 2 rows x 2 views x 160 w.
//  B: half-warp = voxel, lane = channel pair: LDG.64 corner gathers; ref
//     features loaded once, reused for both depth rows.
//  D: thread = w: weights loaded ONCE per k and applied to BOTH rows
//     (weight LDS halved); dx-folded into 9 U values per row via smem edges.
// ---------------------------------------------------------------------------
__global__ void __launch_bounds__(256, 2)
warp_var_kernel(const float* __restrict__ depth_values,
                const float* __restrict__ w_reg)
{
    extern __shared__ char smraw[];
    float4* s_wgt = (float4*)(smraw + OFF_WGT);   // [(r*2+v)*160 + w]
    int4*   s_adr = (int4*)  (smraw + OFF_ADR);
    float*  s_var = (float*) (smraw + OFF_VAR);   // r*5760 + w*36 + c
    ull*    s_pwt = (ull*)   (smraw + OFF_PWT);   // k*16 + c2
    float*  s_e0  = (float*) (smraw + OFF_E0);    // (r*9+k9)*162 + idx
    float*  s_e2  = (float*) (smraw + OFF_E2);

    int h  = blockIdx.x;
    int d0 = blockIdx.y * 2;
    int tid = threadIdx.x;

    // ---- Phase A: projection coords for 2 rows x 2 views x 160 w ----
    for (int t = tid; t < 640; t += 256) {
        int r   = t / 320;
        int rem = t - r*320;
        int v   = rem / 160;
        int w   = rem - v*160;
        float depth = __ldg(depth_values + d0 + r);
        float fx = (float)w, fy = (float)h;

        float px = (g_rot[v][0]*fx + g_rot[v][1]*fy + g_rot[v][2]) * depth + g_trans[v][0];
        float py = (g_rot[v][3]*fx + g_rot[v][4]*fy + g_rot[v][5]) * depth + g_trans[v][1];
        float pz = (g_rot[v][6]*fx + g_rot[v][7]*fy + g_rot[v][8]) * depth + g_trans[v][2];
        float gx = px / pz;
        float gy = py / pz;

        float x0f = floorf(gx), y0f = floorf(gy);
        float wx = gx - x0f, wy = gy - y0f;
        float x1f = x0f + 1.0f, y1f = y0f + 1.0f;

        float vx0 = (x0f >= 0.0f && x0f <= (float)(WW-1)) ? 1.0f : 0.0f;
        float vx1 = (x1f >= 0.0f && x1f <= (float)(WW-1)) ? 1.0f : 0.0f;
        float vy0 = (y0f >= 0.0f && y0f <= (float)(HH-1)) ? 1.0f : 0.0f;
        float vy1 = (y1f >= 0.0f && y1f <= (float)(HH-1)) ? 1.0f : 0.0f;

        float w00 = (1.0f-wx)*(1.0f-wy) * (vx0*vy0);
        float w10 = wx*(1.0f-wy)        * (vx1*vy0);
        float w01 = (1.0f-wx)*wy        * (vx0*vy1);
        float w11 = wx*wy               * (vx1*vy1);

        int x0 = (int)fminf(fmaxf(x0f, 0.0f), (float)(WW-1));
        int x1 = (int)fminf(fmaxf(x1f, 0.0f), (float)(WW-1));
        int y0 = (int)fminf(fmaxf(y0f, 0.0f), (float)(HH-1));
        int y1 = (int)fminf(fmaxf(y1f, 0.0f), (float)(HH-1));

        int si = (r*2 + v)*160 + w;
        s_wgt[si] = make_float4(w00, w10, w01, w11);
        s_adr[si] = make_int4((y0*WW + x0)*16, (y0*WW + x1)*16,
                              (y1*WW + x0)*16, (y1*WW + x1)*16);
    }

    // Packed weights: s_pwt[k*16+c2] = (wt[2c2][k], wt[2c2+1][k])
    for (int i = tid; i < 27*16; i += 256) {
        int k  = i >> 4;
        int c2 = i & 15;
        float lo = __ldg(w_reg + (2*c2    )*27 + k);
        float hi = __ldg(w_reg + (2*c2 + 1)*27 + k);
        ull p; PACK2(p, lo, hi);
        s_pwt[i] = p;
    }
    __syncthreads();

    // ---- Phase B: paired-voxel float2 gathers + variance, both rows ----
    {
        int lane = tid & 31;
        int warp = tid >> 5;
        int half = lane >> 4;          // which voxel of the pair
        int c2   = lane & 15;          // channel pair index

        const float2* F0 = (const float2*)g_featT[0];
        const float2* F1 = (const float2*)g_featT[1];
        const float2* F2 = (const float2*)g_featT[2];

        // ref features: d-independent, load once for both rows
        float2 refs[10];
#pragma unroll
        for (int i = 0; i < 10; ++i) {
            int w = warp*20 + 2*i + half;
            refs[i] = __ldg(F0 + (h*WW + w)*16 + c2);
        }

#pragma unroll
        for (int r = 0; r < 2; ++r) {
            const float4* wgt = s_wgt + (r*2)*160;
            const int4*   adr = s_adr + (r*2)*160;
            float* vr = s_var + r*5760;
#pragma unroll 5
            for (int i = 0; i < 10; ++i) {
                int w = warp*20 + 2*i + half;

                float2 ref = refs[i];
                float sx = ref.x, sy = ref.y;
                float qx = ref.x*ref.x, qy = ref.y*ref.y;

                {
                    float4 wt = wgt[w];
                    int4   ad = adr[w];
                    float2 a = __ldg(F1 + ad.x + c2);
                    float2 b = __ldg(F1 + ad.y + c2);
                    float2 c = __ldg(F1 + ad.z + c2);
                    float2 e = __ldg(F1 + ad.w + c2);
                    float fxv = wt.x*a.x + wt.y*b.x + wt.z*c.x + wt.w*e.x;
                    float fyv = wt.x*a.y + wt.y*b.y + wt.z*c.y + wt.w*e.y;
                    sx += fxv; qx += fxv*fxv;
                    sy += fyv; qy += fyv*fyv;
                }
                {
                    float4 wt = wgt[160 + w];
                    int4   ad = adr[160 + w];
                    float2 a = __ldg(F2 + ad.x + c2);
                    float2 b = __ldg(F2 + ad.y + c2);
                    float2 c = __ldg(F2 + ad.z + c2);
                    float2 e = __ldg(F2 + ad.w + c2);
                    float fxv = wt.x*a.x + wt.y*b.x + wt.z*c.x + wt.w*e.x;
                    float fyv = wt.x*a.y + wt.y*b.y + wt.z*c.y + wt.w*e.y;
                    sx += fxv; qx += fxv*fxv;
                    sy += fyv; qy += fyv*fyv;
                }

                const float inv3 = (1.0f/3.0f);
                float mx = sx * inv3, my = sy * inv3;
                float2 var = make_float2(qx*inv3 - mx*mx, qy*inv3 - my*my);
                *(float2*)(vr + w*36 + 2*c2) = var;
            }
        }
    }
    __syncthreads();   // after this, s_wgt/s_adr are dead -> region becomes edges

    // zero fold-edge boundary cells (2 rows x 9 x 2 edges)
    if (tid < 36) {
        int r  = tid / 18;
        int q  = tid - r*18;
        int a  = q / 9;
        int k9 = q - a*9;
        if (a) s_e2[(r*9 + k9)*162 + 160] = 0.0f;
        else   s_e0[(r*9 + k9)*162 + 0]   = 0.0f;
    }

    // ---- Phase D: dual-row channel GEMM (weights loaded once per k) ----
    float S1a[9], S1b[9];
    if (tid < WW) {
        int w = tid;
        ull va[16], vb[16];
        const ulonglong2* qa = (const ulonglong2*)(s_var + w*36);
        const ulonglong2* qb = (const ulonglong2*)(s_var + 5760 + w*36);
#pragma unroll
        for (int j = 0; j < 8; ++j) {
            ulonglong2 pa = qa[j], pb = qb[j];
            va[2*j] = pa.x; va[2*j+1] = pa.y;
            vb[2*j] = pb.x; vb[2*j+1] = pb.y;
        }

#pragma unroll
        for (int k = 0; k < 27; ++k) {
            const ulonglong2* pw = (const ulonglong2*)(s_pwt + k*16);
            ull aA = 0ull, aB = 0ull, bA = 0ull, bB = 0ull;
#pragma unroll
            for (int c2 = 0; c2 < 8; ++c2) {
                ulonglong2 wp = pw[c2];
                FFMA2(aA, va[2*c2],   wp.x, aA);
                FFMA2(aB, va[2*c2+1], wp.y, aB);
                FFMA2(bA, vb[2*c2],   wp.x, bA);
                FFMA2(bB, vb[2*c2+1], wp.y, bB);
            }
            float x0, x1, y0, y1;
            UNPACK2(x0, x1, aA); UNPACK2(y0, y1, aB);
            float Sa = (x0 + x1) + (y0 + y1);
            UNPACK2(x0, x1, bA); UNPACK2(y0, y1, bB);
            float Sb = (x0 + x1) + (y0 + y1);

            int k9 = k / 3, dx = k - k9*3;
            if (dx == 0) {
                s_e0[(0*9 + k9)*162 + w + 1] = Sa;
                s_e0[(1*9 + k9)*162 + w + 1] = Sb;
            } else if (dx == 1) {
                S1a[k9] = Sa; S1b[k9] = Sb;
            } else {
                s_e2[(0*9 + k9)*162 + w] = Sa;
                s_e2[(1*9 + k9)*162 + w] = Sb;
            }
        }
    }
    __syncthreads();

    if (tid < WW) {
        int w = tid;
        size_t base = (size_t)(d0 + 1)*SLICE + (h + 1)*ROWS + w;
#pragma unroll
        for (int k9 = 0; k9 < 9; ++k9) {
            float Ua = s_e0[(0*9 + k9)*162 + w] + S1a[k9] + s_e2[(0*9 + k9)*162 + w + 1];
            float Ub = s_e0[(1*9 + k9)*162 + w] + S1b[k9] + s_e2[(1*9 + k9)*162 + w + 1];
            g_S[(size_t)k9*CSTS + base]         = Ua;
            g_S[(size_t)k9*CSTS + base + SLICE] = Ub;
        }
    }
}

// ---------------------------------------------------------------------------
// Stage 3: 9-tap shifted-sum of partial volumes -> cost, float4-vectorized.
// cost(d,h,w) = sum_{dz,dy} U_{dz,dy}(padded d+dz, h+dy, w)
// ---------------------------------------------------------------------------
__global__ void __launch_bounds__(256)
sum_kernel()
{
    int idx = blockIdx.x * 256 + threadIdx.x;      // DD*HH*WW/4 = 245760
    int w4 = idx % 40;
    int t  = idx / 40;
    int h  = t % HH;
    int d  = t / HH;

    const float* base = g_S + (size_t)d*SLICE + h*ROWS + w4*4;
    float ax = 0.0f, ay = 0.0f, az = 0.0f, aw = 0.0f;
#pragma unroll
    for (int k9 = 0; k9 < 9; ++k9) {
        int dz = k9 / 3, dy = k9 - dz*3;
        float4 v = *(const float4*)(base + (size_t)k9*CSTS + dz*SLICE + dy*ROWS);
        ax += v.x; ay += v.y; az += v.z; aw += v.w;
    }
    *(float4*)(g_cost + d*HW + h*WW + w4*4) = make_float4(ax, ay, az, aw);
}

// ---------------------------------------------------------------------------
// Stage 4: softmax over D, expected depth + max-prob confidence.
// b_reg shifts all logits equally -> cancels in softmax -> ignored.
// ---------------------------------------------------------------------------
__global__ void __launch_bounds__(128)
depth_kernel(const float* __restrict__ depth_values, float* __restrict__ out)
{
    int pix = blockIdx.x * 128 + threadIdx.x;
    if (pix >= HW) return;

    float cv[DD];
    float m = -1e30f;
#pragma unroll
    for (int d = 0; d < DD; ++d) {
        cv[d] = g_cost[d*HW + pix];
        m = fmaxf(m, cv[d]);
    }
    float sum = 0.0f, dep = 0.0f, best = 0.0f;
#pragma unroll
    for (int d = 0; d < DD; ++d) {
        float e = expf(cv[d] - m);
        sum += e;
        dep += e * __ldg(depth_values + d);
        best = fmaxf(best, e);
    }
    float isum = 1.0f / sum;
    out[pix]      = dep * isum;
    out[HW + pix] = best * isum;
}

// ---------------------------------------------------------------------------
extern "C" void kernel_launch(void* const* d_in, const int* in_sizes, int n_in,
                              void* d_out, int out_size)
{
    const float* feat0 = (const float*)d_in[0];
    const float* feat1 = (const float*)d_in[1];
    const float* feat2 = (const float*)d_in[2];
    const float* proj  = (const float*)d_in[3];
    const float* dvals = (const float*)d_in[4];
    const float* wreg  = (const float*)d_in[5];
    float* out = (float*)d_out;

    cudaFuncSetAttribute(warp_var_kernel,
                         cudaFuncAttributeMaxDynamicSharedMemorySize, SMEM_BYTES);

    prep_kernel<<<1, 1>>>(proj);
    transpose_kernel<<<dim3(HW/32, 3), dim3(32, 8)>>>(feat0, feat1, feat2);
    warp_var_kernel<<<dim3(HH, DD/2), 256, SMEM_BYTES>>>(dvals, wreg);
    sum_kernel<<<(DD*HH*WW/4 + 255)/256, 256>>>();
    depth_kernel<<<(HW + 127)/128, 128>>>(dvals, out);
}